// round 5
// baseline (speedup 1.0000x reference)
#include <cuda_runtime.h>

// UMPS chain contraction: B=64, L=1024, F+1=17, D=32, O=8.
// 128 chains (batch x {left,right}), 512 sequential steps each:
//   v_new[c] = sum_r v[r] * A_s[r,c],  A_s = I + sum_{f=1..16} x_{s,f} C_f
// (channel 0 is structural: inputs[:,:,0]=1, core[:,0,:]=eye).
// left:  A[r,c] = I + sum x_f C[r,f,c];  right: A[r,c] = I + sum x_f C[c,f,r].
//
// Warp-specialized single kernel, 9 warps (R5: occupancy fix — 8 thin
// producer warps instead of 4 fat ones; 2 producers per SMSP interleave to
// hide LDS + FMA-dependency latency that R4's ncu showed fully exposed):
//  - producers (w=1..8): 4 columns each, A_s ahead of the sweep into a
//    16-step transposed smem ring; accumulators init to identity pairs.
//  - consumer (w=0): recursion with no cross-lane reduction.
//  - named bar.arrive/bar.sync, groups of 8 steps, double-buffered ring.
//  - dir=1 block publishes wR + token; dir=0 block spins, computes output.

#define BATCH   64
#define SEQ     1024
#define F1      17
#define NF      16
#define DD      32
#define OO      8
#define HALF    512
#define NCHAIN  128
#define THREADS 288          // 1 consumer + 8 producer warps
#define XS      32           // duplicated-pair row: 16 f * 2 floats (128B)
#define ATS     36           // At row stride (conflict-free LDS.128 / STS.32)
#define STEPF   (DD * ATS)   // 1152 floats per staged A matrix
#define GSTEPS  8
#define RING    16
#define NGROUPS (HALF / GSTEPS)

// smem layout (floats)
#define SM_V    0                          // v double buffer [2][32]
#define SM_AT   64                         // ring (also staging scratch)
#define SM_XS   (SM_AT + RING * STEPF)
#define SMEM_FLOATS (SM_XS + HALF * XS)
#define SMEM_BYTES  (SMEM_FLOATS * 4)      // 139,520 B

__device__ float g_res[BATCH * DD];        // wR per batch (written by dir=1)
__device__ int   g_tok[BATCH];             // monotone handshake tokens

typedef unsigned long long ull;

__device__ __forceinline__ ull pack2(float a, float b) {
    ull r;
    asm("mov.b64 %0, {%1, %2};" : "=l"(r)
        : "r"(__float_as_uint(a)), "r"(__float_as_uint(b)));
    return r;
}
__device__ __forceinline__ void fma2(ull& acc, ull x, ull c) {
    asm("fma.rn.f32x2 %0, %1, %2, %0;" : "+l"(acc) : "l"(x), "l"(c));
}
__device__ __forceinline__ ull add2(ull a, ull b) {
    ull r;
    asm("add.rn.f32x2 %0, %1, %2;" : "=l"(r) : "l"(a), "l"(b));
    return r;
}
__device__ __forceinline__ void unpack2(ull v, float& lo, float& hi) {
    unsigned int a, b;
    asm("mov.b64 {%0, %1}, %2;" : "=r"(a), "=r"(b) : "l"(v));
    lo = __uint_as_float(a);
    hi = __uint_as_float(b);
}
__device__ __forceinline__ void bar_sync_n(int id, int cnt) {
    asm volatile("bar.sync %0, %1;" :: "r"(id), "r"(cnt) : "memory");
}
__device__ __forceinline__ void bar_arrive_n(int id, int cnt) {
    asm volatile("bar.arrive %0, %1;" :: "r"(id), "r"(cnt) : "memory");
}
// barrier ids: FULL slot j -> 1+j ; EMPTY slot j -> 3+j

__global__ __launch_bounds__(THREADS, 1) void sweep_kernel(
    const float* __restrict__ inputs,   // (B, L, F1)
    const float* __restrict__ core,     // (D, F1, D)
    const float* __restrict__ alpha,    // (D)
    const float* __restrict__ omega,    // (D)
    const float* __restrict__ oc,       // (D, O, D)
    float* __restrict__ out)            // (B, O)
{
    extern __shared__ float smem[];
    float* vsm = smem + SM_V;
    float* at  = smem + SM_AT;
    float* xs  = smem + SM_XS;

    const int tid  = threadIdx.x;
    const int lane = tid & 31;
    const int w    = tid >> 5;            // 0 = consumer, 1..8 = producers
    const int bid  = blockIdx.x;
    const int b    = bid >> 1;
    const int dir  = bid & 1;

    // token snapshot FIRST (long before the partner could increment)
    int tok0 = 0;
    if (dir == 0 && tid == 0) tok0 = *(volatile int*)&g_tok[b];

    // ---- pass 1: bulk coalesced copy of this chain's half into scratch ----
    {
        const float4* src = (const float4*)(inputs + (size_t)b * SEQ * F1
                                            + (size_t)dir * HALF * F1);
        float4* dst = (float4*)at;          // scratch (ring reused later)
        for (int i = tid; i < HALF * F1 / 4; i += THREADS) dst[i] = src[i];
    }
    __syncthreads();

    // ---- pass 2: duplicated {x,x} pairs in sweep order (f = 1..16) ----
    {
        const float* raw = at;
        for (int i = tid; i < HALF * NF; i += THREADS) {
            const int s  = i >> 4;
            const int fi = i & 15;
            const int srow = dir ? (HALF - 1 - s) : s;
            const float val = raw[srow * F1 + fi + 1];
            *(float2*)&xs[s * XS + 2 * fi] = make_float2(val, val);
        }
    }
    if (w == 0) vsm[lane] = dir ? omega[lane] : alpha[lane];

    // producer coefficients: 4 cols per warp = 2 packed c-pairs x 16 f
    ull cregA[NF], cregB[NF];
    ull idA = 0ull, idB = 0ull;
    if (w != 0) {
        const int cq = (w - 1) << 2;
        idA = pack2(lane == cq     ? 1.0f : 0.0f, lane == cq + 1 ? 1.0f : 0.0f);
        idB = pack2(lane == cq + 2 ? 1.0f : 0.0f, lane == cq + 3 ? 1.0f : 0.0f);
#pragma unroll
        for (int f = 0; f < NF; f++) {
            if (dir == 0) {
                cregA[f] = pack2(core[(lane * F1 + f + 1) * DD + cq],
                                 core[(lane * F1 + f + 1) * DD + cq + 1]);
                cregB[f] = pack2(core[(lane * F1 + f + 1) * DD + cq + 2],
                                 core[(lane * F1 + f + 1) * DD + cq + 3]);
            } else {
                cregA[f] = pack2(core[(cq * F1 + f + 1) * DD + lane],
                                 core[((cq + 1) * F1 + f + 1) * DD + lane]);
                cregB[f] = pack2(core[((cq + 2) * F1 + f + 1) * DD + lane],
                                 core[((cq + 3) * F1 + f + 1) * DD + lane]);
            }
        }
    }
    __syncthreads();   // scratch consumed; ring free for group 0

    if (w == 0) {
        // ================= consumer: the sequential sweep =================
#pragma unroll 1
        for (int g = 0; g < NGROUPS; g++) {
            bar_sync_n(1 + (g & 1), THREADS);
#pragma unroll
            for (int t = 0; t < GSTEPS; t++) {
                const int s = g * GSTEPS + t;
                const ulonglong2* ap =
                    (const ulonglong2*)&at[(s & (RING - 1)) * STEPF + lane * ATS];
                const ulonglong2* vp =
                    (const ulonglong2*)&vsm[(s & 1) * DD];

                const ulonglong2 a0 = ap[0], a1 = ap[1], a2 = ap[2], a3 = ap[3];
                const ulonglong2 a4 = ap[4], a5 = ap[5], a6 = ap[6], a7 = ap[7];
                const ulonglong2 v0 = vp[0], v1 = vp[1], v2 = vp[2], v3 = vp[3];
                const ulonglong2 v4 = vp[4], v5 = vp[5], v6 = vp[6], v7 = vp[7];

                ull c0 = 0ull, c1 = 0ull, c2 = 0ull, c3 = 0ull;
                fma2(c0, v0.x, a0.x); fma2(c1, v0.y, a0.y);
                fma2(c2, v1.x, a1.x); fma2(c3, v1.y, a1.y);
                fma2(c0, v2.x, a2.x); fma2(c1, v2.y, a2.y);
                fma2(c2, v3.x, a3.x); fma2(c3, v3.y, a3.y);
                fma2(c0, v4.x, a4.x); fma2(c1, v4.y, a4.y);
                fma2(c2, v5.x, a5.x); fma2(c3, v5.y, a5.y);
                fma2(c0, v6.x, a6.x); fma2(c1, v6.y, a6.y);
                fma2(c2, v7.x, a7.x); fma2(c3, v7.y, a7.y);

                const ull tt = add2(add2(c0, c1), add2(c2, c3));
                float lo, hi;
                unpack2(tt, lo, hi);
                vsm[((s + 1) & 1) * DD + lane] = lo + hi;
                __syncwarp();
            }
            bar_arrive_n(3 + (g & 1), THREADS);
        }
        if (dir == 1) {
            g_res[b * DD + lane] = vsm[lane];   // final v in buffer 0 (512 even)
            __threadfence();
            if (lane == 0) atomicAdd(&g_tok[b], 1);
        }
    } else {
        // ================= producers: A matrices ahead of the sweep =======
        const int cq = (w - 1) << 2;
#pragma unroll 1
        for (int g = 0; g < NGROUPS; g++) {
            if (g >= 2) bar_sync_n(3 + (g & 1), THREADS);
#pragma unroll
            for (int t = 0; t < GSTEPS; t++) {
                const int s = g * GSTEPS + t;
                const ulonglong2* xq = (const ulonglong2*)&xs[s * XS];
                const ulonglong2 q0 = xq[0], q1 = xq[1], q2 = xq[2], q3 = xq[3];
                const ulonglong2 q4 = xq[4], q5 = xq[5], q6 = xq[6], q7 = xq[7];

                ull eA = idA, oA = 0ull, eB = idB, oB = 0ull;
                fma2(eA, q0.x, cregA[0]);  fma2(eB, q0.x, cregB[0]);
                fma2(oA, q0.y, cregA[1]);  fma2(oB, q0.y, cregB[1]);
                fma2(eA, q1.x, cregA[2]);  fma2(eB, q1.x, cregB[2]);
                fma2(oA, q1.y, cregA[3]);  fma2(oB, q1.y, cregB[3]);
                fma2(eA, q2.x, cregA[4]);  fma2(eB, q2.x, cregB[4]);
                fma2(oA, q2.y, cregA[5]);  fma2(oB, q2.y, cregB[5]);
                fma2(eA, q3.x, cregA[6]);  fma2(eB, q3.x, cregB[6]);
                fma2(oA, q3.y, cregA[7]);  fma2(oB, q3.y, cregB[7]);
                fma2(eA, q4.x, cregA[8]);  fma2(eB, q4.x, cregB[8]);
                fma2(oA, q4.y, cregA[9]);  fma2(oB, q4.y, cregB[9]);
                fma2(eA, q5.x, cregA[10]); fma2(eB, q5.x, cregB[10]);
                fma2(oA, q5.y, cregA[11]); fma2(oB, q5.y, cregB[11]);
                fma2(eA, q6.x, cregA[12]); fma2(eB, q6.x, cregB[12]);
                fma2(oA, q6.y, cregA[13]); fma2(oB, q6.y, cregB[13]);
                fma2(eA, q7.x, cregA[14]); fma2(eB, q7.x, cregB[14]);
                fma2(oA, q7.y, cregA[15]); fma2(oB, q7.y, cregB[15]);

                float a0, a1, b0, b1;
                unpack2(add2(eA, oA), a0, a1);
                unpack2(add2(eB, oB), b0, b1);
                float* dst = &at[(s & (RING - 1)) * STEPF + lane];
                dst[(cq + 0) * ATS] = a0;
                dst[(cq + 1) * ATS] = a1;
                dst[(cq + 2) * ATS] = b0;
                dst[(cq + 3) * ATS] = b1;
            }
            bar_arrive_n(1 + (g & 1), THREADS);
        }
    }

    // ================= fused finish (dir=0 blocks only) ====================
    __syncthreads();
    if (dir == 0) {
        __shared__ float wsh[DD];
        if (tid == 0) {
            while (*(volatile int*)&g_tok[b] == tok0) { }
            __threadfence();
        }
        __syncthreads();
        if (tid < DD) wsh[tid] = __ldcg(&g_res[b * DD + tid]);
        __syncthreads();
        // out[b,o] = sum_e wR[e] * (sum_d vL[d] * OC[d,o,e]); vL = vsm[0][*]
        if (w < OO) {
            const int o = w;
            float t = 0.0f;
#pragma unroll
            for (int d = 0; d < DD; d++)
                t = fmaf(vsm[d], oc[(d * OO + o) * DD + lane], t);
            t *= wsh[lane];
#pragma unroll
            for (int off = 16; off; off >>= 1)
                t += __shfl_xor_sync(0xffffffffu, t, off);
            if (lane == 0) out[b * OO + o] = t;
        }
    }
}

extern "C" void kernel_launch(void* const* d_in, const int* in_sizes, int n_in,
                              void* d_out, int out_size) {
    const float* inputs = (const float*)d_in[0];   // (64,1024,17)
    const float* core   = (const float*)d_in[1];   // (32,17,32)
    const float* alpha  = (const float*)d_in[2];   // (32)
    const float* omega  = (const float*)d_in[3];   // (32)
    const float* oc     = (const float*)d_in[4];   // (32,8,32)
    float*       out    = (float*)d_out;           // (64,8)

    cudaFuncSetAttribute(sweep_kernel,
                         cudaFuncAttributeMaxDynamicSharedMemorySize, SMEM_BYTES);
    sweep_kernel<<<NCHAIN, THREADS, SMEM_BYTES>>>(inputs, core, alpha, omega, oc, out);
}

// round 6
// speedup vs baseline: 1.1484x; 1.1484x over previous
#include <cuda_runtime.h>

// UMPS chain contraction: B=64, L=1024, F+1=17, D=32, O=8.
// 128 chains (batch x {left,right}), 512 sequential steps each:
//   v_new[c] = sum_r v[r] * A_s[r,c],  A_s = I + sum_{f=1..16} x_{s,f} C_f
// (channel 0 structural: inputs[:,:,0]=1, core[:,0,:]=eye).
// left:  A[r,c] = I + sum x_f C[r,f,c];  right: A[r,c] = I + sum x_f C[c,f,r].
//
// R6: producer x-operands now come from SCALAR broadcast LDS (1 crossbar
// phase each) + pack_dup MOVs on the idle ALU pipe, replacing the broadcast
// LDS.128 of duplicated pairs that R5's ncu showed as the L1 binder
// (128-bit "broadcast" still moves 512B/warp through the crossbar).
//  - 8 producer warps (4 cols each): A_s ahead of the sweep into a 16-step
//    transposed smem ring; accumulators init to identity pairs.
//  - 1 consumer warp: recursion with no cross-lane reduction.
//  - named bar.arrive/bar.sync, groups of 8 steps, double-buffered ring.
//  - dir=1 block publishes wR + token; dir=0 block spins, computes output.

#define BATCH   64
#define SEQ     1024
#define F1      17
#define NF      16
#define DD      32
#define OO      8
#define HALF    512
#define NCHAIN  128
#define THREADS 288          // 1 consumer + 8 producer warps
#define XS      16           // plain x row: 16 floats (64B)
#define ATS     36           // At row stride (conflict-free for LDS.128 phases)
#define STEPF   (DD * ATS)   // 1152 floats per staged A matrix
#define GSTEPS  8
#define RING    16
#define NGROUPS (HALF / GSTEPS)

// smem layout (floats)
#define SM_V    0                          // v double buffer [2][32]
#define SM_AT   64                         // ring (also staging scratch)
#define SM_XS   (SM_AT + RING * STEPF)
#define SMEM_FLOATS (SM_XS + HALF * XS)
#define SMEM_BYTES  (SMEM_FLOATS * 4)      // 106,752 B

__device__ float g_res[BATCH * DD];        // wR per batch (written by dir=1)
__device__ int   g_tok[BATCH];             // monotone handshake tokens

typedef unsigned long long ull;

__device__ __forceinline__ ull pack2(float a, float b) {
    ull r;
    asm("mov.b64 %0, {%1, %2};" : "=l"(r)
        : "r"(__float_as_uint(a)), "r"(__float_as_uint(b)));
    return r;
}
__device__ __forceinline__ ull pack_dup(float x) {
    ull r;
    unsigned int xb = __float_as_uint(x);
    asm("mov.b64 %0, {%1, %1};" : "=l"(r) : "r"(xb));
    return r;
}
__device__ __forceinline__ void fma2(ull& acc, ull x, ull c) {
    asm("fma.rn.f32x2 %0, %1, %2, %0;" : "+l"(acc) : "l"(x), "l"(c));
}
__device__ __forceinline__ ull add2(ull a, ull b) {
    ull r;
    asm("add.rn.f32x2 %0, %1, %2;" : "=l"(r) : "l"(a), "l"(b));
    return r;
}
__device__ __forceinline__ void unpack2(ull v, float& lo, float& hi) {
    unsigned int a, b;
    asm("mov.b64 {%0, %1}, %2;" : "=r"(a), "=r"(b) : "l"(v));
    lo = __uint_as_float(a);
    hi = __uint_as_float(b);
}
__device__ __forceinline__ void bar_sync_n(int id, int cnt) {
    asm volatile("bar.sync %0, %1;" :: "r"(id), "r"(cnt) : "memory");
}
__device__ __forceinline__ void bar_arrive_n(int id, int cnt) {
    asm volatile("bar.arrive %0, %1;" :: "r"(id), "r"(cnt) : "memory");
}
// barrier ids: FULL slot j -> 1+j ; EMPTY slot j -> 3+j

__global__ __launch_bounds__(THREADS, 1) void sweep_kernel(
    const float* __restrict__ inputs,   // (B, L, F1)
    const float* __restrict__ core,     // (D, F1, D)
    const float* __restrict__ alpha,    // (D)
    const float* __restrict__ omega,    // (D)
    const float* __restrict__ oc,       // (D, O, D)
    float* __restrict__ out)            // (B, O)
{
    extern __shared__ float smem[];
    float* vsm = smem + SM_V;
    float* at  = smem + SM_AT;
    float* xs  = smem + SM_XS;

    const int tid  = threadIdx.x;
    const int lane = tid & 31;
    const int w    = tid >> 5;            // 0 = consumer, 1..8 = producers
    const int bid  = blockIdx.x;
    const int b    = bid >> 1;
    const int dir  = bid & 1;

    // token snapshot FIRST (long before the partner could increment)
    int tok0 = 0;
    if (dir == 0 && tid == 0) tok0 = *(volatile int*)&g_tok[b];

    // ---- pass 1: bulk coalesced copy of this chain's half into scratch ----
    {
        const float4* src = (const float4*)(inputs + (size_t)b * SEQ * F1
                                            + (size_t)dir * HALF * F1);
        float4* dst = (float4*)at;          // scratch (ring reused later)
        for (int i = tid; i < HALF * F1 / 4; i += THREADS) dst[i] = src[i];
    }
    __syncthreads();

    // ---- pass 2: plain x rows (f = 1..16) in sweep order ----
    {
        const float* raw = at;
        for (int i = tid; i < HALF * NF; i += THREADS) {
            const int s  = i >> 4;
            const int fi = i & 15;
            const int srow = dir ? (HALF - 1 - s) : s;
            xs[s * XS + fi] = raw[srow * F1 + fi + 1];
        }
    }
    if (w == 0) vsm[lane] = dir ? omega[lane] : alpha[lane];

    // producer coefficients: 4 cols per warp = 2 packed c-pairs x 16 f
    ull cregA[NF], cregB[NF];
    ull idA = 0ull, idB = 0ull;
    if (w != 0) {
        const int cq = (w - 1) << 2;
        idA = pack2(lane == cq     ? 1.0f : 0.0f, lane == cq + 1 ? 1.0f : 0.0f);
        idB = pack2(lane == cq + 2 ? 1.0f : 0.0f, lane == cq + 3 ? 1.0f : 0.0f);
#pragma unroll
        for (int f = 0; f < NF; f++) {
            if (dir == 0) {
                cregA[f] = pack2(core[(lane * F1 + f + 1) * DD + cq],
                                 core[(lane * F1 + f + 1) * DD + cq + 1]);
                cregB[f] = pack2(core[(lane * F1 + f + 1) * DD + cq + 2],
                                 core[(lane * F1 + f + 1) * DD + cq + 3]);
            } else {
                cregA[f] = pack2(core[(cq * F1 + f + 1) * DD + lane],
                                 core[((cq + 1) * F1 + f + 1) * DD + lane]);
                cregB[f] = pack2(core[((cq + 2) * F1 + f + 1) * DD + lane],
                                 core[((cq + 3) * F1 + f + 1) * DD + lane]);
            }
        }
    }
    __syncthreads();   // scratch consumed; ring free for group 0

    if (w == 0) {
        // ================= consumer: the sequential sweep =================
#pragma unroll 1
        for (int g = 0; g < NGROUPS; g++) {
            bar_sync_n(1 + (g & 1), THREADS);
#pragma unroll
            for (int t = 0; t < GSTEPS; t++) {
                const int s = g * GSTEPS + t;
                const ulonglong2* ap =
                    (const ulonglong2*)&at[(s & (RING - 1)) * STEPF + lane * ATS];
                const ulonglong2* vp =
                    (const ulonglong2*)&vsm[(s & 1) * DD];

                const ulonglong2 a0 = ap[0], a1 = ap[1], a2 = ap[2], a3 = ap[3];
                const ulonglong2 a4 = ap[4], a5 = ap[5], a6 = ap[6], a7 = ap[7];
                const ulonglong2 v0 = vp[0], v1 = vp[1], v2 = vp[2], v3 = vp[3];
                const ulonglong2 v4 = vp[4], v5 = vp[5], v6 = vp[6], v7 = vp[7];

                ull c0 = 0ull, c1 = 0ull, c2 = 0ull, c3 = 0ull;
                fma2(c0, v0.x, a0.x); fma2(c1, v0.y, a0.y);
                fma2(c2, v1.x, a1.x); fma2(c3, v1.y, a1.y);
                fma2(c0, v2.x, a2.x); fma2(c1, v2.y, a2.y);
                fma2(c2, v3.x, a3.x); fma2(c3, v3.y, a3.y);
                fma2(c0, v4.x, a4.x); fma2(c1, v4.y, a4.y);
                fma2(c2, v5.x, a5.x); fma2(c3, v5.y, a5.y);
                fma2(c0, v6.x, a6.x); fma2(c1, v6.y, a6.y);
                fma2(c2, v7.x, a7.x); fma2(c3, v7.y, a7.y);

                const ull tt = add2(add2(c0, c1), add2(c2, c3));
                float lo, hi;
                unpack2(tt, lo, hi);
                vsm[((s + 1) & 1) * DD + lane] = lo + hi;
                __syncwarp();
            }
            bar_arrive_n(3 + (g & 1), THREADS);
        }
        if (dir == 1) {
            g_res[b * DD + lane] = vsm[lane];   // final v in buffer 0 (512 even)
            __threadfence();
            if (lane == 0) atomicAdd(&g_tok[b], 1);
        }
    } else {
        // ================= producers: A matrices ahead of the sweep =======
        const int cq = (w - 1) << 2;
#pragma unroll 1
        for (int g = 0; g < NGROUPS; g++) {
            if (g >= 2) bar_sync_n(3 + (g & 1), THREADS);
#pragma unroll
            for (int t = 0; t < GSTEPS; t++) {
                const int s = g * GSTEPS + t;
                const float* xr = &xs[s * XS];
                // 16 scalar broadcast LDS (1 phase each), then ALU-pipe dups
                float x0 = xr[0],  x1 = xr[1],  x2 = xr[2],  x3 = xr[3];
                float x4 = xr[4],  x5 = xr[5],  x6 = xr[6],  x7 = xr[7];
                float x8 = xr[8],  x9 = xr[9],  xA = xr[10], xB = xr[11];
                float xC = xr[12], xD = xr[13], xE = xr[14], xF = xr[15];
                const ull d0 = pack_dup(x0), d1 = pack_dup(x1);
                const ull d2 = pack_dup(x2), d3 = pack_dup(x3);
                const ull d4 = pack_dup(x4), d5 = pack_dup(x5);
                const ull d6 = pack_dup(x6), d7 = pack_dup(x7);
                const ull d8 = pack_dup(x8), d9 = pack_dup(x9);
                const ull dA = pack_dup(xA), dB = pack_dup(xB);
                const ull dC = pack_dup(xC), dD = pack_dup(xD);
                const ull dE = pack_dup(xE), dF = pack_dup(xF);

                ull eA = idA, oA = 0ull, eB = idB, oB = 0ull;
                fma2(eA, d0, cregA[0]);  fma2(eB, d0, cregB[0]);
                fma2(oA, d1, cregA[1]);  fma2(oB, d1, cregB[1]);
                fma2(eA, d2, cregA[2]);  fma2(eB, d2, cregB[2]);
                fma2(oA, d3, cregA[3]);  fma2(oB, d3, cregB[3]);
                fma2(eA, d4, cregA[4]);  fma2(eB, d4, cregB[4]);
                fma2(oA, d5, cregA[5]);  fma2(oB, d5, cregB[5]);
                fma2(eA, d6, cregA[6]);  fma2(eB, d6, cregB[6]);
                fma2(oA, d7, cregA[7]);  fma2(oB, d7, cregB[7]);
                fma2(eA, d8, cregA[8]);  fma2(eB, d8, cregB[8]);
                fma2(oA, d9, cregA[9]);  fma2(oB, d9, cregB[9]);
                fma2(eA, dA, cregA[10]); fma2(eB, dA, cregB[10]);
                fma2(oA, dB, cregA[11]); fma2(oB, dB, cregB[11]);
                fma2(eA, dC, cregA[12]); fma2(eB, dC, cregB[12]);
                fma2(oA, dD, cregA[13]); fma2(oB, dD, cregB[13]);
                fma2(eA, dE, cregA[14]); fma2(eB, dE, cregB[14]);
                fma2(oA, dF, cregA[15]); fma2(oB, dF, cregB[15]);

                float a0, a1, b0, b1;
                unpack2(add2(eA, oA), a0, a1);
                unpack2(add2(eB, oB), b0, b1);
                float* dst = &at[(s & (RING - 1)) * STEPF + lane];
                dst[(cq + 0) * ATS] = a0;
                dst[(cq + 1) * ATS] = a1;
                dst[(cq + 2) * ATS] = b0;
                dst[(cq + 3) * ATS] = b1;
            }
            bar_arrive_n(1 + (g & 1), THREADS);
        }
    }

    // ================= fused finish (dir=0 blocks only) ====================
    __syncthreads();
    if (dir == 0) {
        __shared__ float wsh[DD];
        if (tid == 0) {
            while (*(volatile int*)&g_tok[b] == tok0) { }
            __threadfence();
        }
        __syncthreads();
        if (tid < DD) wsh[tid] = __ldcg(&g_res[b * DD + tid]);
        __syncthreads();
        // out[b,o] = sum_e wR[e] * (sum_d vL[d] * OC[d,o,e]); vL = vsm[0][*]
        if (w < OO) {
            const int o = w;
            float t = 0.0f;
#pragma unroll
            for (int d = 0; d < DD; d++)
                t = fmaf(vsm[d], oc[(d * OO + o) * DD + lane], t);
            t *= wsh[lane];
#pragma unroll
            for (int off = 16; off; off >>= 1)
                t += __shfl_xor_sync(0xffffffffu, t, off);
            if (lane == 0) out[b * OO + o] = t;
        }
    }
}

extern "C" void kernel_launch(void* const* d_in, const int* in_sizes, int n_in,
                              void* d_out, int out_size) {
    const float* inputs = (const float*)d_in[0];   // (64,1024,17)
    const float* core   = (const float*)d_in[1];   // (32,17,32)
    const float* alpha  = (const float*)d_in[2];   // (32)
    const float* omega  = (const float*)d_in[3];   // (32)
    const float* oc     = (const float*)d_in[4];   // (32,8,32)
    float*       out    = (float*)d_out;           // (64,8)

    cudaFuncSetAttribute(sweep_kernel,
                         cudaFuncAttributeMaxDynamicSharedMemorySize, SMEM_BYTES);
    sweep_kernel<<<NCHAIN, THREADS, SMEM_BYTES>>>(inputs, core, alpha, omega, oc, out);
}